// round 1
// baseline (speedup 1.0000x reference)
#include <cuda_runtime.h>
#include <cstddef>

#define D_MODEL 1024
#define N_HEADS 16
#define D_HEAD 64
#define BATCH 2
#define SEQ 2048
#define M_ROWS (BATCH * SEQ)   // 4096

// Scratch (allocation-free rule: device globals)
__device__ float g_qkv[(size_t)M_ROWS * 3 * D_MODEL];   // [4096, 3072]
__device__ float g_ctx[(size_t)M_ROWS * D_MODEL];       // [4096, 1024]

// ---------------------------------------------------------------------------
// Generic row-major fp32 GEMM: C[M,N] = A[M,K] @ B[K,N]
// Tile: BM=64, BN=64, BK=16, 256 threads, 4x4 micro-tile per thread.
// M,N,K are all multiples of the tile sizes for this problem -> no guards.
// ---------------------------------------------------------------------------
__global__ __launch_bounds__(256)
void gemm64_kernel(const float* __restrict__ A, const float* __restrict__ Bm,
                   float* __restrict__ C, int M, int N, int K)
{
    __shared__ float As[16][64];   // [k][m]
    __shared__ float Bs[16][64];   // [k][n]

    const int tid = threadIdx.x;
    const int tx  = tid & 15;      // 0..15  (n direction)
    const int ty  = tid >> 4;      // 0..15  (m direction)
    const int row0 = blockIdx.y * 64;
    const int col0 = blockIdx.x * 64;

    float acc[4][4];
#pragma unroll
    for (int i = 0; i < 4; i++)
#pragma unroll
        for (int j = 0; j < 4; j++) acc[i][j] = 0.0f;

    for (int k0 = 0; k0 < K; k0 += 16) {
        // Load A tile (64 rows x 16 k), transpose into As[k][m]
        {
            const int m  = tid >> 2;          // 0..63
            const int k4 = (tid & 3) * 4;     // 0,4,8,12
            float4 a = *(const float4*)&A[(size_t)(row0 + m) * K + k0 + k4];
            As[k4 + 0][m] = a.x;
            As[k4 + 1][m] = a.y;
            As[k4 + 2][m] = a.z;
            As[k4 + 3][m] = a.w;
        }
        // Load B tile (16 k x 64 n)
        {
            const int r  = tid >> 4;          // 0..15
            const int c4 = (tid & 15) * 4;    // 0..60
            *(float4*)&Bs[r][c4] = *(const float4*)&Bm[(size_t)(k0 + r) * N + col0 + c4];
        }
        __syncthreads();

#pragma unroll
        for (int k = 0; k < 16; k++) {
            float4 a4 = *(const float4*)&As[k][ty * 4];
            float4 b4 = *(const float4*)&Bs[k][tx * 4];
            float av[4] = {a4.x, a4.y, a4.z, a4.w};
            float bv[4] = {b4.x, b4.y, b4.z, b4.w};
#pragma unroll
            for (int i = 0; i < 4; i++)
#pragma unroll
                for (int j = 0; j < 4; j++)
                    acc[i][j] += av[i] * bv[j];
        }
        __syncthreads();
    }

#pragma unroll
    for (int i = 0; i < 4; i++) {
        const int r = row0 + ty * 4 + i;
        *(float4*)&C[(size_t)r * N + col0 + tx * 4] =
            make_float4(acc[i][0], acc[i][1], acc[i][2], acc[i][3]);
    }
}

// ---------------------------------------------------------------------------
// Causal flash attention, fp32.
// Grid: (SEQ/128, BATCH*N_HEADS), 128 threads. Thread i owns query row
// t = blockIdx.x*128 + i. q and the output accumulator live in registers
// (16 float4 each). K/V are staged in 64-key smem tiles.
// qkv layout: [b, t, 3*D_MODEL] with the 3072 dim = s*1024 + h*64 + d.
// ---------------------------------------------------------------------------
__global__ __launch_bounds__(128)
void attn_kernel(const float* __restrict__ qkv, float* __restrict__ ctx)
{
    __shared__ float Ks[64][64];
    __shared__ float Vs[64][64];

    const int tid = threadIdx.x;                 // 0..127
    const int bh  = blockIdx.y;
    const int b   = bh >> 4;
    const int h   = bh & 15;
    const int t   = blockIdx.x * 128 + tid;      // this thread's query row
    const float scale = 0.125f;                  // 1/sqrt(64)

    const float* qrow = qkv + (size_t)(b * SEQ + t) * (3 * D_MODEL) + h * D_HEAD;

    float4 q4[16];
    float4 a4[16];
#pragma unroll
    for (int i = 0; i < 16; i++) {
        float4 v = *(const float4*)&qrow[i * 4];
        q4[i] = make_float4(v.x * scale, v.y * scale, v.z * scale, v.w * scale);
        a4[i] = make_float4(0.f, 0.f, 0.f, 0.f);
    }

    float m = -1e30f;
    float l = 0.0f;
    const int tmax = blockIdx.x * 128 + 127;     // last row handled by block

    for (int j0 = 0; j0 <= tmax; j0 += 64) {
        // Cooperatively load K and V tiles (64 keys x 64 dims)
#pragma unroll
        for (int i = 0; i < 8; i++) {
            const int lidx = tid + 128 * i;      // 0..1023
            const int r    = lidx >> 4;          // key within tile
            const int c4   = (lidx & 15) * 4;    // dim
            const float* base = qkv + (size_t)(b * SEQ + j0 + r) * (3 * D_MODEL)
                                    + h * D_HEAD + c4;
            *(float4*)&Ks[r][c4] = *(const float4*)(base + D_MODEL);
            *(float4*)&Vs[r][c4] = *(const float4*)(base + 2 * D_MODEL);
        }
        __syncthreads();

        int jend = t - j0 + 1;                   // causal limit within tile
        if (jend > 64) jend = 64;

        for (int j = 0; j < jend; j++) {
            const float4* kk = (const float4*)&Ks[j][0];
            // 4 independent partial sums to break the FMA dependency chain
            float s0 = 0.f, s1 = 0.f, s2 = 0.f, s3 = 0.f;
#pragma unroll
            for (int i = 0; i < 16; i++) {
                float4 kv = kk[i];
                s0 += q4[i].x * kv.x;
                s1 += q4[i].y * kv.y;
                s2 += q4[i].z * kv.z;
                s3 += q4[i].w * kv.w;
            }
            float s = (s0 + s1) + (s2 + s3);

            if (s > m) {                          // rare (~log T times per row)
                float corr = __expf(m - s);
                l *= corr;
#pragma unroll
                for (int i = 0; i < 16; i++) {
                    a4[i].x *= corr; a4[i].y *= corr;
                    a4[i].z *= corr; a4[i].w *= corr;
                }
                m = s;
            }
            float p = __expf(s - m);
            l += p;

            const float4* vv = (const float4*)&Vs[j][0];
#pragma unroll
            for (int i = 0; i < 16; i++) {
                float4 v = vv[i];
                a4[i].x += p * v.x; a4[i].y += p * v.y;
                a4[i].z += p * v.z; a4[i].w += p * v.w;
            }
        }
        __syncthreads();
    }

    const float inv = 1.0f / l;
    float* out = ctx + (size_t)(b * SEQ + t) * D_MODEL + h * D_HEAD;
#pragma unroll
    for (int i = 0; i < 16; i++) {
        *(float4*)&out[i * 4] = make_float4(a4[i].x * inv, a4[i].y * inv,
                                            a4[i].z * inv, a4[i].w * inv);
    }
}

// ---------------------------------------------------------------------------
extern "C" void kernel_launch(void* const* d_in, const int* in_sizes, int n_in,
                              void* d_out, int out_size)
{
    const float* x      = (const float*)d_in[0];   // [2,2048,1024]
    const float* w_qkv  = (const float*)d_in[1];   // [1024,3072]
    const float* w_proj = (const float*)d_in[2];   // [1024,1024]
    float* out = (float*)d_out;                    // [2,2048,1024]

    float* qkv = nullptr;
    float* ctx = nullptr;
    cudaGetSymbolAddress((void**)&qkv, g_qkv);
    cudaGetSymbolAddress((void**)&ctx, g_ctx);

    // 1) QKV GEMM: [4096,1024] @ [1024,3072] -> [4096,3072]
    {
        dim3 grid(3 * D_MODEL / 64, M_ROWS / 64);
        gemm64_kernel<<<grid, 256>>>(x, w_qkv, qkv, M_ROWS, 3 * D_MODEL, D_MODEL);
    }

    // 2) Causal attention -> ctx [4096,1024]
    {
        dim3 grid(SEQ / 128, BATCH * N_HEADS);
        attn_kernel<<<grid, 128>>>(qkv, ctx);
    }

    // 3) Projection GEMM: [4096,1024] @ [1024,1024] -> out
    {
        dim3 grid(D_MODEL / 64, M_ROWS / 64);
        gemm64_kernel<<<grid, 256>>>(ctx, w_proj, out, M_ROWS, D_MODEL, D_MODEL);
    }
}

// round 2
// speedup vs baseline: 2.4684x; 2.4684x over previous
#include <cuda_runtime.h>
#include <cstdint>
#include <cstddef>

#define D_MODEL 1024
#define N_HEADS 16
#define D_HEAD 64
#define BATCH 2
#define SEQ 2048
#define M_ROWS (BATCH * SEQ)   // 4096

// Scratch (allocation-free rule: device globals)
__device__ float g_qkv[(size_t)M_ROWS * 3 * D_MODEL];   // [4096, 3072]
__device__ float g_ctx[(size_t)M_ROWS * D_MODEL];       // [4096, 1024]

// ---------------------------------------------------------------------------
// tf32 helpers
// ---------------------------------------------------------------------------
__device__ __forceinline__ uint32_t f2tf(float f) {
    uint32_t u;
    asm("cvt.rna.tf32.f32 %0, %1;" : "=r"(u) : "f"(f));
    return u;
}

// D += A @ B  (m16n8k8, tf32 in, fp32 accumulate)
__device__ __forceinline__ void mma8(float4& d, const uint32_t* a, const uint32_t* b) {
    asm volatile(
        "mma.sync.aligned.m16n8k8.row.col.f32.tf32.tf32.f32 "
        "{%0,%1,%2,%3},{%4,%5,%6,%7},{%8,%9},{%0,%1,%2,%3};"
        : "+f"(d.x), "+f"(d.y), "+f"(d.z), "+f"(d.w)
        : "r"(a[0]), "r"(a[1]), "r"(a[2]), "r"(a[3]),
          "r"(b[0]), "r"(b[1]));
}

// ---------------------------------------------------------------------------
// GEMM: C[M,N] = A[M,K] @ B[K,N], fp32 in/out, tf32 tensor cores.
// Block tile 128x128x16, 256 threads = 8 warps (2x4), warp tile 64x32.
// Double-buffered smem. Padded strides -> conflict-free fragment loads.
// Requires M%128==0, N%128==0, K%16==0.
// ---------------------------------------------------------------------------
#define ASTR 20    // A smem row stride (words): banks (20g + c) % 32 distinct
#define BSTR 136   // B smem row stride (words): banks (8c + g) % 32 distinct

__global__ __launch_bounds__(256, 2)
void gemm_tf32(const float* __restrict__ A, const float* __restrict__ B,
               float* __restrict__ C, int M, int N, int K)
{
    __shared__ uint32_t As[2][128 * ASTR];
    __shared__ uint32_t Bs[2][16 * BSTR];

    const int tid  = threadIdx.x;
    const int lane = tid & 31;
    const int warp = tid >> 5;
    const int g    = lane >> 2;
    const int c    = lane & 3;
    const int wm   = (warp & 1) * 64;
    const int wn   = (warp >> 1) * 32;
    const int row0 = blockIdx.y * 128;
    const int col0 = blockIdx.x * 128;

    // global staging assignments
    const int ar = tid >> 1,  ac = (tid & 1) * 8;    // A: 128 rows x 16 k
    const int br = tid >> 4,  bc = (tid & 15) * 8;   // B: 16 k x 128 n
    const float* gA = A + (size_t)(row0 + ar) * K + ac;
    const float* gB = B + (size_t)br * N + col0 + bc;

    float4 sa0 = *(const float4*)(gA);
    float4 sa1 = *(const float4*)(gA + 4);
    float4 sb0 = *(const float4*)(gB);
    float4 sb1 = *(const float4*)(gB + 4);

    float4 acc[4][4];
#pragma unroll
    for (int i = 0; i < 4; ++i)
#pragma unroll
        for (int j = 0; j < 4; ++j) acc[i][j] = make_float4(0.f, 0.f, 0.f, 0.f);

    const int iters = K / 16;
    int buf = 0;

    for (int it = 0; it < iters; ++it) {
        // store staged tile (converted to tf32) into smem[buf]
        {
            uint32_t* as = &As[buf][ar * ASTR + ac];
            as[0] = f2tf(sa0.x); as[1] = f2tf(sa0.y); as[2] = f2tf(sa0.z); as[3] = f2tf(sa0.w);
            as[4] = f2tf(sa1.x); as[5] = f2tf(sa1.y); as[6] = f2tf(sa1.z); as[7] = f2tf(sa1.w);
            uint32_t* bs = &Bs[buf][br * BSTR + bc];
            bs[0] = f2tf(sb0.x); bs[1] = f2tf(sb0.y); bs[2] = f2tf(sb0.z); bs[3] = f2tf(sb0.w);
            bs[4] = f2tf(sb1.x); bs[5] = f2tf(sb1.y); bs[6] = f2tf(sb1.z); bs[7] = f2tf(sb1.w);
        }
        __syncthreads();

        // prefetch next k-slab
        if (it + 1 < iters) {
            const float* pa = gA + (it + 1) * 16;
            sa0 = *(const float4*)(pa);
            sa1 = *(const float4*)(pa + 4);
            const float* pb = gB + (size_t)(it + 1) * 16 * N;
            sb0 = *(const float4*)(pb);
            sb1 = *(const float4*)(pb + 4);
        }

        // compute on smem[buf]
#pragma unroll
        for (int ks = 0; ks < 2; ++ks) {
            const int kk = ks * 8;
            uint32_t af[4][4];
            uint32_t bf[4][2];
#pragma unroll
            for (int i = 0; i < 4; ++i) {
                const uint32_t* p = &As[buf][(wm + i * 16 + g) * ASTR + kk + c];
                af[i][0] = p[0];
                af[i][1] = p[8 * ASTR];
                af[i][2] = p[4];
                af[i][3] = p[8 * ASTR + 4];
            }
#pragma unroll
            for (int j = 0; j < 4; ++j) {
                const uint32_t* p = &Bs[buf][(kk + c) * BSTR + wn + j * 8 + g];
                bf[j][0] = p[0];
                bf[j][1] = p[4 * BSTR];
            }
#pragma unroll
            for (int i = 0; i < 4; ++i)
#pragma unroll
                for (int j = 0; j < 4; ++j)
                    mma8(acc[i][j], af[i], bf[j]);
        }
        __syncthreads();
        buf ^= 1;
    }

    // epilogue: accumulator layout c0:(g,2c) c1:(g,2c+1) c2:(g+8,2c) c3:(g+8,2c+1)
#pragma unroll
    for (int i = 0; i < 4; ++i) {
        const int r = row0 + wm + i * 16 + g;
#pragma unroll
        for (int j = 0; j < 4; ++j) {
            const int cl = col0 + wn + j * 8 + 2 * c;
            *(float2*)&C[(size_t)r * N + cl]       = make_float2(acc[i][j].x, acc[i][j].y);
            *(float2*)&C[(size_t)(r + 8) * N + cl] = make_float2(acc[i][j].z, acc[i][j].w);
        }
    }
}

// ---------------------------------------------------------------------------
// Flash attention, causal, tf32 tensor cores.
// Br=64 query rows per CTA (4 warps, 16 rows each), Bc=64 key tiles.
// Q fragments register-resident; K tile smem is reused for the P tile.
// qkv layout: [b, t, 3*D_MODEL], split dim = s*1024 + h*64 + d.
// ---------------------------------------------------------------------------
#define KSTR 68   // K/P smem row stride: banks (4g + c) % 32 distinct
#define VSTR 72   // V smem row stride:   banks (8c + g) % 32 distinct

__global__ __launch_bounds__(128)
void fa_tf32(const float* __restrict__ qkv, float* __restrict__ ctx)
{
    __shared__ uint32_t KPs[64 * KSTR];   // K tile, then P tile
    __shared__ uint32_t Vs[64 * VSTR];

    const int tid  = threadIdx.x;
    const int lane = tid & 31;
    const int warp = tid >> 5;
    const int g    = lane >> 2;
    const int c    = lane & 3;
    const int bh   = blockIdx.y;
    const int b    = bh >> 4;
    const int h    = bh & 15;
    const int q0   = blockIdx.x * 64;

    const float* qbase = qkv + (size_t)(b * SEQ) * 3072 + h * 64;

    // Q fragments (rows q0 + warp*16 + g / +8), pre-scaled, tf32
    uint32_t qf[8][4];
    {
        const float* r0 = qbase + (size_t)(q0 + warp * 16 + g) * 3072;
        const float* r1 = r0 + 8 * 3072;
        const float sc = 0.125f;   // 1/sqrt(64)
#pragma unroll
        for (int ks = 0; ks < 8; ++ks) {
            qf[ks][0] = f2tf(r0[ks * 8 + c] * sc);
            qf[ks][1] = f2tf(r1[ks * 8 + c] * sc);
            qf[ks][2] = f2tf(r0[ks * 8 + c + 4] * sc);
            qf[ks][3] = f2tf(r1[ks * 8 + c + 4] * sc);
        }
    }

    float4 oacc[8];
#pragma unroll
    for (int i = 0; i < 8; ++i) oacc[i] = make_float4(0.f, 0.f, 0.f, 0.f);
    float m0 = -1e30f, m1 = -1e30f, l0 = 0.f, l1 = 0.f;

    const int kr = tid >> 1;           // 0..63 (K/V staging row)
    const int kc = (tid & 1) * 32;     // half-row

    for (int j0 = 0; j0 <= q0; j0 += 64) {
        __syncthreads();   // protect KPs (prev P) / Vs before overwrite
        // cooperative K/V tile load (tf32)
        {
            const float* kg = qbase + (size_t)(j0 + kr) * 3072 + 1024 + kc;
            const float* vg = kg + 1024;
            uint32_t* kd = &KPs[kr * KSTR + kc];
            uint32_t* vd = &Vs[kr * VSTR + kc];
#pragma unroll
            for (int i = 0; i < 8; ++i) {
                float4 kv = *(const float4*)(kg + i * 4);
                kd[i * 4 + 0] = f2tf(kv.x); kd[i * 4 + 1] = f2tf(kv.y);
                kd[i * 4 + 2] = f2tf(kv.z); kd[i * 4 + 3] = f2tf(kv.w);
                float4 vv = *(const float4*)(vg + i * 4);
                vd[i * 4 + 0] = f2tf(vv.x); vd[i * 4 + 1] = f2tf(vv.y);
                vd[i * 4 + 2] = f2tf(vv.z); vd[i * 4 + 3] = f2tf(vv.w);
            }
        }
        __syncthreads();

        // ---- S = (Q*scale) @ K^T ----
        float4 sacc[8];
#pragma unroll
        for (int i = 0; i < 8; ++i) sacc[i] = make_float4(0.f, 0.f, 0.f, 0.f);
#pragma unroll
        for (int ks = 0; ks < 8; ++ks) {
            uint32_t bf[8][2];
#pragma unroll
            for (int nt = 0; nt < 8; ++nt) {
                const uint32_t* p = &KPs[(nt * 8 + g) * KSTR + ks * 8 + c];
                bf[nt][0] = p[0];
                bf[nt][1] = p[4];
            }
#pragma unroll
            for (int nt = 0; nt < 8; ++nt) mma8(sacc[nt], qf[ks], bf[nt]);
        }

        // ---- causal mask (only the diagonal tile needs it) ----
        if (j0 == q0) {
            const int ra = warp * 16 + g;   // local row == local col origin
#pragma unroll
            for (int nt = 0; nt < 8; ++nt) {
                const int cl = nt * 8 + 2 * c;
                if (cl     > ra)     sacc[nt].x = -1e30f;
                if (cl + 1 > ra)     sacc[nt].y = -1e30f;
                if (cl     > ra + 8) sacc[nt].z = -1e30f;
                if (cl + 1 > ra + 8) sacc[nt].w = -1e30f;
            }
        }

        // ---- online softmax update ----
        float tm0 = -1e30f, tm1 = -1e30f;
#pragma unroll
        for (int nt = 0; nt < 8; ++nt) {
            tm0 = fmaxf(tm0, fmaxf(sacc[nt].x, sacc[nt].y));
            tm1 = fmaxf(tm1, fmaxf(sacc[nt].z, sacc[nt].w));
        }
        tm0 = fmaxf(tm0, __shfl_xor_sync(0xffffffffu, tm0, 1));
        tm0 = fmaxf(tm0, __shfl_xor_sync(0xffffffffu, tm0, 2));
        tm1 = fmaxf(tm1, __shfl_xor_sync(0xffffffffu, tm1, 1));
        tm1 = fmaxf(tm1, __shfl_xor_sync(0xffffffffu, tm1, 2));
        const float nm0 = fmaxf(m0, tm0);
        const float nm1 = fmaxf(m1, tm1);
        const float cr0 = __expf(m0 - nm0);
        const float cr1 = __expf(m1 - nm1);
        m0 = nm0; m1 = nm1;

        float ps0 = 0.f, ps1 = 0.f;
#pragma unroll
        for (int nt = 0; nt < 8; ++nt) {
            sacc[nt].x = __expf(sacc[nt].x - m0);
            sacc[nt].y = __expf(sacc[nt].y - m0);
            sacc[nt].z = __expf(sacc[nt].z - m1);
            sacc[nt].w = __expf(sacc[nt].w - m1);
            ps0 += sacc[nt].x + sacc[nt].y;
            ps1 += sacc[nt].z + sacc[nt].w;
        }
        ps0 += __shfl_xor_sync(0xffffffffu, ps0, 1);
        ps0 += __shfl_xor_sync(0xffffffffu, ps0, 2);
        ps1 += __shfl_xor_sync(0xffffffffu, ps1, 1);
        ps1 += __shfl_xor_sync(0xffffffffu, ps1, 2);
        l0 = l0 * cr0 + ps0;
        l1 = l1 * cr1 + ps1;
#pragma unroll
        for (int nt = 0; nt < 8; ++nt) {
            oacc[nt].x *= cr0; oacc[nt].y *= cr0;
            oacc[nt].z *= cr1; oacc[nt].w *= cr1;
        }

        __syncthreads();   // every warp finished reading the K tile

        // ---- store P (tf32) over the K tile ----
        {
            const int ra = warp * 16 + g;
#pragma unroll
            for (int nt = 0; nt < 8; ++nt) {
                uint32_t* p0 = &KPs[ra * KSTR + nt * 8 + 2 * c];
                p0[0] = f2tf(sacc[nt].x);
                p0[1] = f2tf(sacc[nt].y);
                uint32_t* p1 = p0 + 8 * KSTR;
                p1[0] = f2tf(sacc[nt].z);
                p1[1] = f2tf(sacc[nt].w);
            }
        }
        __syncwarp();   // warp reads back only its own 16 P rows

        // ---- O += P @ V ----
#pragma unroll
        for (int ks = 0; ks < 8; ++ks) {
            uint32_t af[4];
            const uint32_t* p = &KPs[(warp * 16 + g) * KSTR + ks * 8 + c];
            af[0] = p[0];
            af[1] = p[8 * KSTR];
            af[2] = p[4];
            af[3] = p[8 * KSTR + 4];
            uint32_t bf[8][2];
#pragma unroll
            for (int nt = 0; nt < 8; ++nt) {
                const uint32_t* q = &Vs[(ks * 8 + c) * VSTR + nt * 8 + g];
                bf[nt][0] = q[0];
                bf[nt][1] = q[4 * VSTR];
            }
#pragma unroll
            for (int nt = 0; nt < 8; ++nt) mma8(oacc[nt], af, bf[nt]);
        }
    }

    // ---- normalize + write ctx ----
    const float il0 = 1.f / l0;
    const float il1 = 1.f / l1;
    float* o0 = ctx + (size_t)(b * SEQ + q0 + warp * 16 + g) * 1024 + h * 64;
    float* o1 = o0 + 8 * 1024;
#pragma unroll
    for (int nt = 0; nt < 8; ++nt) {
        *(float2*)(o0 + nt * 8 + 2 * c) = make_float2(oacc[nt].x * il0, oacc[nt].y * il0);
        *(float2*)(o1 + nt * 8 + 2 * c) = make_float2(oacc[nt].z * il1, oacc[nt].w * il1);
    }
}

// ---------------------------------------------------------------------------
extern "C" void kernel_launch(void* const* d_in, const int* in_sizes, int n_in,
                              void* d_out, int out_size)
{
    const float* x      = (const float*)d_in[0];   // [2,2048,1024]
    const float* w_qkv  = (const float*)d_in[1];   // [1024,3072]
    const float* w_proj = (const float*)d_in[2];   // [1024,1024]
    float* out = (float*)d_out;                    // [2,2048,1024]

    float* qkv = nullptr;
    float* ctx = nullptr;
    cudaGetSymbolAddress((void**)&qkv, g_qkv);
    cudaGetSymbolAddress((void**)&ctx, g_ctx);

    // 1) QKV GEMM: [4096,1024] @ [1024,3072]
    {
        dim3 grid(3 * D_MODEL / 128, M_ROWS / 128);
        gemm_tf32<<<grid, 256>>>(x, w_qkv, qkv, M_ROWS, 3 * D_MODEL, D_MODEL);
    }
    // 2) Causal flash attention
    {
        dim3 grid(SEQ / 64, BATCH * N_HEADS);
        fa_tf32<<<grid, 128>>>(qkv, ctx);
    }
    // 3) Projection GEMM: [4096,1024] @ [1024,1024]
    {
        dim3 grid(D_MODEL / 128, M_ROWS / 128);
        gemm_tf32<<<grid, 256>>>(ctx, w_proj, out, M_ROWS, D_MODEL, D_MODEL);
    }
}

// round 3
// speedup vs baseline: 3.2766x; 1.3274x over previous
#include <cuda_runtime.h>
#include <cstdint>
#include <cstddef>

#define D_MODEL 1024
#define N_HEADS 16
#define D_HEAD 64
#define BATCH 2
#define SEQ 2048
#define M_ROWS (BATCH * SEQ)   // 4096

// Scratch (allocation-free rule: device globals)
__device__ float g_qkv[(size_t)M_ROWS * 3 * D_MODEL];   // [4096, 3072]
__device__ float g_ctx[(size_t)M_ROWS * D_MODEL];       // [4096, 1024]

// ---------------------------------------------------------------------------
// helpers
// ---------------------------------------------------------------------------
__device__ __forceinline__ uint32_t f2tf(float f) {
    uint32_t u;
    asm("cvt.rna.tf32.f32 %0, %1;" : "=r"(u) : "f"(f));
    return u;
}
__device__ __forceinline__ float ex2(float x) {
    float r;
    asm("ex2.approx.ftz.f32 %0, %1;" : "=f"(r) : "f"(x));
    return r;
}
__device__ __forceinline__ void mma8(float4& d, const uint32_t* a, const uint32_t* b) {
    asm volatile(
        "mma.sync.aligned.m16n8k8.row.col.f32.tf32.tf32.f32 "
        "{%0,%1,%2,%3},{%4,%5,%6,%7},{%8,%9},{%0,%1,%2,%3};"
        : "+f"(d.x), "+f"(d.y), "+f"(d.z), "+f"(d.w)
        : "r"(a[0]), "r"(a[1]), "r"(a[2]), "r"(a[3]),
          "r"(b[0]), "r"(b[1]));
}
__device__ __forceinline__ void cpa16(uint32_t dst, const void* src) {
    asm volatile("cp.async.cg.shared.global [%0], [%1], 16;\n" :: "r"(dst), "l"(src));
}

// ---------------------------------------------------------------------------
// GEMM: C[M,N] = A[M,K] @ B[K,N], fp32 in/out, tf32 tensor cores.
// 128x128x16 block tile, 8 warps (2x4), warp tile 64x32, cp.async 4-stage.
// smem holds raw fp32; cvt.rna fused into fragment loads.
// ---------------------------------------------------------------------------
#define ASTR 20    // (20g + c) % 32 all distinct -> conflict-free A frags
#define BSTR 136   // (8c + g) % 32 all distinct  -> conflict-free B frags
#define STAGES 4
#define GEMM_SMEM (STAGES * (128 * ASTR + 16 * BSTR) * 4)   // 75776 B

__global__ __launch_bounds__(256, 2)
void gemm_tf32(const float* __restrict__ A, const float* __restrict__ B,
               float* __restrict__ C, int M, int N, int K)
{
    extern __shared__ float sm[];
    float* As = sm;                           // [STAGES][128*ASTR]
    float* Bs = sm + STAGES * 128 * ASTR;     // [STAGES][16*BSTR]

    const int tid  = threadIdx.x;
    const int lane = tid & 31;
    const int warp = tid >> 5;
    const int g    = lane >> 2;
    const int c    = lane & 3;
    const int wm   = (warp & 1) * 64;
    const int wn   = (warp >> 1) * 32;
    const int row0 = blockIdx.y * 128;
    const int col0 = blockIdx.x * 128;

    const int ar = tid >> 1,  ak = (tid & 1) * 8;    // A: 128 rows x 16 k
    const int br = tid >> 4,  bc = (tid & 15) * 8;   // B: 16 k x 128 n
    const float* gA = A + (size_t)(row0 + ar) * K + ak;
    const float* gB = B + (size_t)br * N + col0 + bc;

    const uint32_t sA = (uint32_t)__cvta_generic_to_shared(As) + (ar * ASTR + ak) * 4;
    const uint32_t sB = (uint32_t)__cvta_generic_to_shared(Bs) + (br * BSTR + bc) * 4;

    const int iters = K / 16;

    auto issue = [&](int slab, int stage) {
        uint32_t da = sA + stage * (128 * ASTR * 4);
        const float* pa = gA + slab * 16;
        cpa16(da, pa);
        cpa16(da + 16, pa + 4);
        uint32_t db = sB + stage * (16 * BSTR * 4);
        const float* pb = gB + (size_t)slab * 16 * N;
        cpa16(db, pb);
        cpa16(db + 16, pb + 4);
    };

#pragma unroll
    for (int s = 0; s < STAGES - 1; ++s) {
        issue(s, s);
        asm volatile("cp.async.commit_group;\n");
    }

    float4 acc[4][4];
#pragma unroll
    for (int i = 0; i < 4; ++i)
#pragma unroll
        for (int j = 0; j < 4; ++j) acc[i][j] = make_float4(0.f, 0.f, 0.f, 0.f);

    for (int it = 0; it < iters; ++it) {
        asm volatile("cp.async.wait_group %0;\n" :: "n"(STAGES - 2));
        __syncthreads();

        if (it + STAGES - 1 < iters)
            issue(it + STAGES - 1, (it + STAGES - 1) & (STAGES - 1));
        asm volatile("cp.async.commit_group;\n");

        const float* as = As + (it & (STAGES - 1)) * (128 * ASTR);
        const float* bs = Bs + (it & (STAGES - 1)) * (16 * BSTR);

#pragma unroll
        for (int ks = 0; ks < 2; ++ks) {
            const int kk = ks * 8;
            uint32_t af[4][4];
            uint32_t bf[4][2];
#pragma unroll
            for (int i = 0; i < 4; ++i) {
                const float* p = as + (wm + i * 16 + g) * ASTR + kk + c;
                af[i][0] = f2tf(p[0]);
                af[i][1] = f2tf(p[8 * ASTR]);
                af[i][2] = f2tf(p[4]);
                af[i][3] = f2tf(p[8 * ASTR + 4]);
            }
#pragma unroll
            for (int j = 0; j < 4; ++j) {
                const float* p = bs + (kk + c) * BSTR + wn + j * 8 + g;
                bf[j][0] = f2tf(p[0]);
                bf[j][1] = f2tf(p[4 * BSTR]);
            }
#pragma unroll
            for (int i = 0; i < 4; ++i)
#pragma unroll
                for (int j = 0; j < 4; ++j)
                    mma8(acc[i][j], af[i], bf[j]);
        }
    }

#pragma unroll
    for (int i = 0; i < 4; ++i) {
        const int r = row0 + wm + i * 16 + g;
#pragma unroll
        for (int j = 0; j < 4; ++j) {
            const int cl = col0 + wn + j * 8 + 2 * c;
            *(float2*)&C[(size_t)r * N + cl]       = make_float2(acc[i][j].x, acc[i][j].y);
            *(float2*)&C[(size_t)(r + 8) * N + cl] = make_float2(acc[i][j].z, acc[i][j].w);
        }
    }
}

// ---------------------------------------------------------------------------
// Flash attention, causal, tf32 tensor cores.
// Br=128 (8 warps x 16 q-rows), Bc=64. Q frags + O accumulator in registers.
// Separate P smem region -> 2 syncthreads per tile. exp2-domain softmax.
// qkv layout: [b, t, 3*D_MODEL], split dim = s*1024 + h*64 + d.
// ---------------------------------------------------------------------------
#define KSTR 68   // (4g + c) % 32 distinct  -> conflict-free K/P frag loads
#define VSTR 72   // (8c + g) % 32 distinct  -> conflict-free V frag loads
#define PSTR 68
#define FA_SMEM ((64 * KSTR + 64 * VSTR + 128 * PSTR) * 4)   // 70656 B

__global__ __launch_bounds__(256, 2)
void fa_tf32(const float* __restrict__ qkv, float* __restrict__ ctx)
{
    extern __shared__ uint32_t fsm[];
    uint32_t* Ks = fsm;                 // [64][KSTR]
    uint32_t* Vs = Ks + 64 * KSTR;      // [64][VSTR]
    uint32_t* Ps = Vs + 64 * VSTR;      // [128][PSTR]

    const int tid  = threadIdx.x;
    const int lane = tid & 31;
    const int warp = tid >> 5;
    const int g    = lane >> 2;
    const int c    = lane & 3;
    const int bh   = blockIdx.y;
    const int b    = bh >> 4;
    const int h    = bh & 15;
    const int q0   = (gridDim.x - 1 - blockIdx.x) * 128;  // big blocks first
    const int wrow = warp * 16;

    const float* qbase = qkv + (size_t)(b * SEQ) * 3072 + h * 64;

    // Q fragments, pre-scaled by (1/sqrt(64)) * log2(e)  (exp2-domain softmax)
    uint32_t qf[8][4];
    {
        const float sc = 0.125f * 1.44269504088896f;
        const float* r0 = qbase + (size_t)(q0 + wrow + g) * 3072;
        const float* r1 = r0 + 8 * 3072;
#pragma unroll
        for (int ks = 0; ks < 8; ++ks) {
            qf[ks][0] = f2tf(r0[ks * 8 + c] * sc);
            qf[ks][1] = f2tf(r1[ks * 8 + c] * sc);
            qf[ks][2] = f2tf(r0[ks * 8 + c + 4] * sc);
            qf[ks][3] = f2tf(r1[ks * 8 + c + 4] * sc);
        }
    }

    float4 oacc[8];
#pragma unroll
    for (int i = 0; i < 8; ++i) oacc[i] = make_float4(0.f, 0.f, 0.f, 0.f);
    float m0 = -1e30f, m1 = -1e30f, l0 = 0.f, l1 = 0.f;

    const int kr  = tid >> 2;           // 0..63 staging row
    const int kc0 = (tid & 3) * 16;     // staging col quarter

    const int jmax = q0 + 64;
    for (int j0 = 0; j0 <= jmax; j0 += 64) {
        // ---- cooperative K/V tile staging (tf32) ----
        {
            const float* kg = qbase + (size_t)(j0 + kr) * 3072 + 1024 + kc0;
            const float* vg = kg + 1024;
            uint32_t* kd = &Ks[kr * KSTR + kc0];
            uint32_t* vd = &Vs[kr * VSTR + kc0];
#pragma unroll
            for (int i = 0; i < 4; ++i) {
                float4 kv = *(const float4*)(kg + i * 4);
                kd[i * 4 + 0] = f2tf(kv.x); kd[i * 4 + 1] = f2tf(kv.y);
                kd[i * 4 + 2] = f2tf(kv.z); kd[i * 4 + 3] = f2tf(kv.w);
                float4 vv = *(const float4*)(vg + i * 4);
                vd[i * 4 + 0] = f2tf(vv.x); vd[i * 4 + 1] = f2tf(vv.y);
                vd[i * 4 + 2] = f2tf(vv.z); vd[i * 4 + 3] = f2tf(vv.w);
            }
        }
        __syncthreads();

        if (j0 <= q0 + wrow + 15) {   // warp has >= 1 unmasked row in this tile
            // ---- S = Q @ K^T ----
            float4 sacc[8];
#pragma unroll
            for (int i = 0; i < 8; ++i) sacc[i] = make_float4(0.f, 0.f, 0.f, 0.f);
#pragma unroll
            for (int ks = 0; ks < 8; ++ks) {
#pragma unroll
                for (int nt = 0; nt < 8; ++nt) {
                    const uint32_t* p = &Ks[(nt * 8 + g) * KSTR + ks * 8 + c];
                    uint32_t bfr[2] = { p[0], p[4] };
                    mma8(sacc[nt], qf[ks], bfr);
                }
            }

            // ---- causal mask ----
            if (j0 + 63 > q0 + wrow) {
                const int rg = q0 + wrow + g;
#pragma unroll
                for (int nt = 0; nt < 8; ++nt) {
                    const int cl = j0 + nt * 8 + 2 * c;
                    if (cl     > rg)     sacc[nt].x = -1e30f;
                    if (cl + 1 > rg)     sacc[nt].y = -1e30f;
                    if (cl     > rg + 8) sacc[nt].z = -1e30f;
                    if (cl + 1 > rg + 8) sacc[nt].w = -1e30f;
                }
            }

            // ---- online softmax (exp2 domain) ----
            float tm0 = -1e30f, tm1 = -1e30f;
#pragma unroll
            for (int nt = 0; nt < 8; ++nt) {
                tm0 = fmaxf(tm0, fmaxf(sacc[nt].x, sacc[nt].y));
                tm1 = fmaxf(tm1, fmaxf(sacc[nt].z, sacc[nt].w));
            }
            tm0 = fmaxf(tm0, __shfl_xor_sync(0xffffffffu, tm0, 1));
            tm0 = fmaxf(tm0, __shfl_xor_sync(0xffffffffu, tm0, 2));
            tm1 = fmaxf(tm1, __shfl_xor_sync(0xffffffffu, tm1, 1));
            tm1 = fmaxf(tm1, __shfl_xor_sync(0xffffffffu, tm1, 2));
            const float nm0 = fmaxf(m0, tm0);
            const float nm1 = fmaxf(m1, tm1);
            const float cr0 = ex2(m0 - nm0);
            const float cr1 = ex2(m1 - nm1);
            m0 = nm0; m1 = nm1;

            float ps0 = 0.f, ps1 = 0.f;
#pragma unroll
            for (int nt = 0; nt < 8; ++nt) {
                sacc[nt].x = ex2(sacc[nt].x - m0);
                sacc[nt].y = ex2(sacc[nt].y - m0);
                sacc[nt].z = ex2(sacc[nt].z - m1);
                sacc[nt].w = ex2(sacc[nt].w - m1);
                ps0 += sacc[nt].x + sacc[nt].y;
                ps1 += sacc[nt].z + sacc[nt].w;
            }
            ps0 += __shfl_xor_sync(0xffffffffu, ps0, 1);
            ps0 += __shfl_xor_sync(0xffffffffu, ps0, 2);
            ps1 += __shfl_xor_sync(0xffffffffu, ps1, 1);
            ps1 += __shfl_xor_sync(0xffffffffu, ps1, 2);
            l0 = l0 * cr0 + ps0;
            l1 = l1 * cr1 + ps1;
#pragma unroll
            for (int nt = 0; nt < 8; ++nt) {
                oacc[nt].x *= cr0; oacc[nt].y *= cr0;
                oacc[nt].z *= cr1; oacc[nt].w *= cr1;
            }

            // ---- store P into warp-private rows (tf32) ----
#pragma unroll
            for (int nt = 0; nt < 8; ++nt) {
                uint32_t* p0 = &Ps[(wrow + g) * PSTR + nt * 8 + 2 * c];
                p0[0] = f2tf(sacc[nt].x);
                p0[1] = f2tf(sacc[nt].y);
                uint32_t* p1 = p0 + 8 * PSTR;
                p1[0] = f2tf(sacc[nt].z);
                p1[1] = f2tf(sacc[nt].w);
            }
            __syncwarp();

            // ---- O += P @ V ----
#pragma unroll
            for (int ks = 0; ks < 8; ++ks) {
                uint32_t af[4];
                const uint32_t* p = &Ps[(wrow + g) * PSTR + ks * 8 + c];
                af[0] = p[0];
                af[1] = p[8 * PSTR];
                af[2] = p[4];
                af[3] = p[8 * PSTR + 4];
#pragma unroll
                for (int nt = 0; nt < 8; ++nt) {
                    const uint32_t* q = &Vs[(ks * 8 + c) * VSTR + nt * 8 + g];
                    uint32_t bfr[2] = { q[0], q[4 * VSTR] };
                    mma8(oacc[nt], af, bfr);
                }
            }
        }
        __syncthreads();   // all warps done with K/V before next staging
    }

    // ---- normalize + write ctx ----
    const float il0 = 1.f / l0;
    const float il1 = 1.f / l1;
    float* o0 = ctx + (size_t)(b * SEQ + q0 + wrow + g) * 1024 + h * 64;
    float* o1 = o0 + 8 * 1024;
#pragma unroll
    for (int nt = 0; nt < 8; ++nt) {
        *(float2*)(o0 + nt * 8 + 2 * c) = make_float2(oacc[nt].x * il0, oacc[nt].y * il0);
        *(float2*)(o1 + nt * 8 + 2 * c) = make_float2(oacc[nt].z * il1, oacc[nt].w * il1);
    }
}

// ---------------------------------------------------------------------------
extern "C" void kernel_launch(void* const* d_in, const int* in_sizes, int n_in,
                              void* d_out, int out_size)
{
    const float* x      = (const float*)d_in[0];   // [2,2048,1024]
    const float* w_qkv  = (const float*)d_in[1];   // [1024,3072]
    const float* w_proj = (const float*)d_in[2];   // [1024,1024]
    float* out = (float*)d_out;                    // [2,2048,1024]

    float* qkv = nullptr;
    float* ctx = nullptr;
    cudaGetSymbolAddress((void**)&qkv, g_qkv);
    cudaGetSymbolAddress((void**)&ctx, g_ctx);

    // Opt-in to >48KB dynamic smem (sticky per-function attribute; harmless
    // if the call is a no-op on subsequent invocations).
    cudaFuncSetAttribute(gemm_tf32, cudaFuncAttributeMaxDynamicSharedMemorySize, GEMM_SMEM);
    cudaFuncSetAttribute(fa_tf32,   cudaFuncAttributeMaxDynamicSharedMemorySize, FA_SMEM);

    // 1) QKV GEMM: [4096,1024] @ [1024,3072]
    {
        dim3 grid(3 * D_MODEL / 128, M_ROWS / 128);
        gemm_tf32<<<grid, 256, GEMM_SMEM>>>(x, w_qkv, qkv, M_ROWS, 3 * D_MODEL, D_MODEL);
    }
    // 2) Causal flash attention
    {
        dim3 grid(SEQ / 128, BATCH * N_HEADS);
        fa_tf32<<<grid, 256, FA_SMEM>>>(qkv, ctx);
    }
    // 3) Projection GEMM: [4096,1024] @ [1024,1024]
    {
        dim3 grid(D_MODEL / 128, M_ROWS / 128);
        gemm_tf32<<<grid, 256, GEMM_SMEM>>>(ctx, w_proj, out, M_ROWS, D_MODEL, D_MODEL);
    }
}

// round 5
// speedup vs baseline: 7.6360x; 2.3305x over previous
#include <cuda_runtime.h>
#include <cuda_fp16.h>
#include <cstdint>
#include <cstddef>

#define D_MODEL 1024
#define N_HEADS 16
#define D_HEAD 64
#define BATCH 2
#define SEQ 2048
#define M_ROWS (BATCH * SEQ)   // 4096

// Scratch (allocation-free rule: device globals)
__device__ __half g_qkv[(size_t)M_ROWS * 3 * D_MODEL];     // [4096,3072] fp16
__device__ __half g_ctx[(size_t)M_ROWS * D_MODEL];         // [4096,1024] fp16
__device__ __half g_xh[(size_t)M_ROWS * D_MODEL];          // fp16(x)
__device__ __half g_wqkvh[(size_t)D_MODEL * 3 * D_MODEL];  // fp16(w_qkv) [K,N]
__device__ __half g_wprojh[(size_t)D_MODEL * D_MODEL];     // fp16(w_proj) [K,N]

// ---------------------------------------------------------------------------
// helpers
// ---------------------------------------------------------------------------
__device__ __forceinline__ float ex2(float x) {
    float r;
    asm("ex2.approx.ftz.f32 %0, %1;" : "=f"(r) : "f"(x));
    return r;
}
__device__ __forceinline__ void cpa16(uint32_t dst, const void* src) {
    asm volatile("cp.async.cg.shared.global [%0], [%1], 16;\n" :: "r"(dst), "l"(src));
}
__device__ __forceinline__ uint32_t sm_u32(const void* p) {
    return (uint32_t)__cvta_generic_to_shared(p);
}
__device__ __forceinline__ void ldsm4(uint32_t& r0, uint32_t& r1, uint32_t& r2, uint32_t& r3,
                                      uint32_t addr) {
    asm volatile("ldmatrix.sync.aligned.m8n8.x4.shared.b16 {%0,%1,%2,%3}, [%4];"
                 : "=r"(r0), "=r"(r1), "=r"(r2), "=r"(r3) : "r"(addr));
}
__device__ __forceinline__ void ldsm4t(uint32_t& r0, uint32_t& r1, uint32_t& r2, uint32_t& r3,
                                       uint32_t addr) {
    asm volatile("ldmatrix.sync.aligned.m8n8.x4.trans.shared.b16 {%0,%1,%2,%3}, [%4];"
                 : "=r"(r0), "=r"(r1), "=r"(r2), "=r"(r3) : "r"(addr));
}
// D += A @ B  (m16n8k16, fp16 in, fp32 accumulate)
__device__ __forceinline__ void mma16(float4& d, const uint32_t* a, const uint32_t* b) {
    asm volatile(
        "mma.sync.aligned.m16n8k16.row.col.f32.f16.f16.f32 "
        "{%0,%1,%2,%3},{%4,%5,%6,%7},{%8,%9},{%0,%1,%2,%3};"
        : "+f"(d.x), "+f"(d.y), "+f"(d.z), "+f"(d.w)
        : "r"(a[0]), "r"(a[1]), "r"(a[2]), "r"(a[3]),
          "r"(b[0]), "r"(b[1]));
}

// ---------------------------------------------------------------------------
// prep: fp32 -> fp16 convert (4 elems / thread)
// ---------------------------------------------------------------------------
__global__ void f2h(const float4* __restrict__ in, __half2* __restrict__ out) {
    const int i = blockIdx.x * blockDim.x + threadIdx.x;
    float4 v = in[i];
    out[i * 2]     = __floats2half2_rn(v.x, v.y);
    out[i * 2 + 1] = __floats2half2_rn(v.z, v.w);
}

// ---------------------------------------------------------------------------
// GEMM: C[M,N] = A[M,1024] @ B[1024,N], fp16 in, fp32 accum, fp16/fp32 out.
// 128x128x32 block tile, 8 warps (2x4), warp tile 64x32, 4-stage cp.async.
// A smem: [128 rows][stride 40 fp16] (80B rows; banks 20r+4c partition 32)
// B smem: [32 k][128 n fp16], 16B chunk swizz ch^(k&7) (conflict-free trans)
// ---------------------------------------------------------------------------
#define GSTAGES 4
#define A_STB (128 * 80)    // 10240 B / stage
#define B_STB (32 * 256)    // 8192 B / stage
#define GEMM_SMEM (GSTAGES * (A_STB + B_STB))   // 73728 B

template<bool HALF_OUT>
__global__ __launch_bounds__(256, 2)
void gemm_h(const __half* __restrict__ A, const __half* __restrict__ B,
            void* __restrict__ Cv, int N)
{
    extern __shared__ char smc[];
    const uint32_t Ab = sm_u32(smc);
    const uint32_t Bb = Ab + GSTAGES * A_STB;

    const int tid  = threadIdx.x;
    const int lane = tid & 31;
    const int warp = tid >> 5;
    const int g    = lane >> 2;
    const int c    = lane & 3;
    const int l15  = lane & 15;
    const int l16  = lane >> 4;
    const int wm   = (warp & 1) * 64;
    const int wn   = (warp >> 1) * 32;
    const int m0   = blockIdx.y * 128;
    const int n0   = blockIdx.x * 128;

    auto stage = [&](int ch) {
        const int s  = ch & 3;
        const int k0 = ch * 32;
#pragma unroll
        for (int i = 0; i < 2; ++i) {              // A: 128 rows x 4 chunks
            const int id = tid + 256 * i;
            const int row = id >> 2, cc = id & 3;
            cpa16(Ab + s * A_STB + row * 80 + cc * 16,
                  A + (size_t)(m0 + row) * 1024 + k0 + cc * 8);
        }
#pragma unroll
        for (int i = 0; i < 2; ++i) {              // B: 32 k x 16 chunks
            const int id = tid + 256 * i;
            const int row = id >> 4, cc = id & 15;
            cpa16(Bb + s * B_STB + row * 256 + ((cc ^ (row & 7)) * 16),
                  B + (size_t)(k0 + row) * N + n0 + cc * 8);
        }
    };

    stage(0); asm volatile("cp.async.commit_group;\n");
    stage(1); asm volatile("cp.async.commit_group;\n");
    stage(2); asm volatile("cp.async.commit_group;\n");

    float4 acc[4][4];
#pragma unroll
    for (int i = 0; i < 4; ++i)
#pragma unroll
        for (int j = 0; j < 4; ++j) acc[i][j] = make_float4(0.f, 0.f, 0.f, 0.f);

    for (int ch = 0; ch < 32; ++ch) {
        asm volatile("cp.async.wait_group %0;\n" :: "n"(2));
        __syncthreads();

        if (ch + 3 < 32) stage(ch + 3);
        asm volatile("cp.async.commit_group;\n");

        const uint32_t As = Ab + (ch & 3) * A_STB;
        const uint32_t Bs = Bb + (ch & 3) * B_STB;

#pragma unroll
        for (int kc = 0; kc < 2; ++kc) {
            uint32_t af[4][4];
#pragma unroll
            for (int i = 0; i < 4; ++i)
                ldsm4(af[i][0], af[i][1], af[i][2], af[i][3],
                      As + (wm + i * 16 + l15) * 80 + (kc * 2 + l16) * 16);
            uint32_t bf[4][2];
#pragma unroll
            for (int j2 = 0; j2 < 2; ++j2) {
                const int krow = kc * 16 + l15;
                const int cn   = (wn >> 3) + j2 * 2 + l16;
                ldsm4t(bf[j2 * 2][0], bf[j2 * 2][1], bf[j2 * 2 + 1][0], bf[j2 * 2 + 1][1],
                       Bs + krow * 256 + ((cn ^ (krow & 7)) * 16));
            }
#pragma unroll
            for (int i = 0; i < 4; ++i)
#pragma unroll
                for (int j = 0; j < 4; ++j)
                    mma16(acc[i][j], af[i], bf[j]);
        }
    }

    // epilogue
#pragma unroll
    for (int i = 0; i < 4; ++i) {
        const int r = m0 + wm + i * 16 + g;
#pragma unroll
        for (int j = 0; j < 4; ++j) {
            const int cl = n0 + wn + j * 8 + 2 * c;
            if (HALF_OUT) {
                __half* C = (__half*)Cv;
                *(__half2*)&C[(size_t)r * N + cl] =
                    __floats2half2_rn(acc[i][j].x, acc[i][j].y);
                *(__half2*)&C[(size_t)(r + 8) * N + cl] =
                    __floats2half2_rn(acc[i][j].z, acc[i][j].w);
            } else {
                float* C = (float*)Cv;
                *(float2*)&C[(size_t)r * N + cl] = make_float2(acc[i][j].x, acc[i][j].y);
                *(float2*)&C[(size_t)(r + 8) * N + cl] = make_float2(acc[i][j].z, acc[i][j].w);
            }
        }
    }
}

// ---------------------------------------------------------------------------
// Flash attention, causal, fp16 mma + ldmatrix.
// Br=128 (8 warps x 16 q-rows), Bc=64. K/V staged via cp.async (fp16),
// P tile in smem fp16. Softmax scale folded post-mma (exp2 domain).
// K/V/P smem rows stride 72 fp16 = 144 B (conflict-free ldmatrix).
// ---------------------------------------------------------------------------
#define KV_B (64 * 144)                    // 9216 B per K / V tile
#define FA_SMEM (2 * KV_B + 128 * 144)     // 36864 B

__global__ __launch_bounds__(256, 2)
void fa_h(const __half* __restrict__ qkv, __half* __restrict__ ctx)
{
    extern __shared__ char fsc[];
    const uint32_t Kb = sm_u32(fsc);
    const uint32_t Vb = Kb + KV_B;
    const uint32_t Pb = Vb + KV_B;

    const int tid  = threadIdx.x;
    const int lane = tid & 31;
    const int warp = tid >> 5;
    const int g    = lane >> 2;
    const int c    = lane & 3;
    const int l15  = lane & 15;
    const int l16  = lane >> 4;
    const int bh   = blockIdx.y;
    const int b    = bh >> 4;
    const int h    = bh & 15;
    const int q0   = (gridDim.x - 1 - blockIdx.x) * 128;   // big blocks first
    const int wrow = warp * 16;

    const __half* qbase = qkv + (size_t)(b * SEQ) * 3072 + h * 64;

    // Q fragments (fp16 pairs straight from gmem)
    uint32_t qf[4][4];
    {
        const __half* r0 = qbase + (size_t)(q0 + wrow + g) * 3072;
        const __half* r1 = r0 + 8 * 3072;
#pragma unroll
        for (int kc = 0; kc < 4; ++kc) {
            qf[kc][0] = *(const uint32_t*)(r0 + kc * 16 + 2 * c);
            qf[kc][1] = *(const uint32_t*)(r1 + kc * 16 + 2 * c);
            qf[kc][2] = *(const uint32_t*)(r0 + kc * 16 + 8 + 2 * c);
            qf[kc][3] = *(const uint32_t*)(r1 + kc * 16 + 8 + 2 * c);
        }
    }

    float4 oacc[8];
#pragma unroll
    for (int i = 0; i < 8; ++i) oacc[i] = make_float4(0.f, 0.f, 0.f, 0.f);
    float m0 = -1e30f, m1 = -1e30f, l0 = 0.f, l1 = 0.f;

    const float SC = 0.125f * 1.44269504088896f;   // (1/sqrt(64)) * log2(e)

    const int jmax = q0 + 64;
    for (int j0 = 0; j0 <= jmax; j0 += 64) {
        // ---- K/V tile staging: cp.async, 64 rows x 8 chunks each ----
#pragma unroll
        for (int i = 0; i < 2; ++i) {
            const int id = tid + 256 * i;          // 0..511
            const int row = id >> 3, cc = id & 7;
            const __half* kg = qbase + (size_t)(j0 + row) * 3072 + 1024 + cc * 8;
            cpa16(Kb + row * 144 + cc * 16, kg);
            cpa16(Vb + row * 144 + cc * 16, kg + 1024);
        }
        asm volatile("cp.async.commit_group;\n");
        asm volatile("cp.async.wait_group 0;\n");
        __syncthreads();

        if (j0 <= q0 + wrow + 15) {   // warp has >= 1 unmasked row in this tile
            // ---- S = Q @ K^T ----
            float4 sacc[8];
#pragma unroll
            for (int i = 0; i < 8; ++i) sacc[i] = make_float4(0.f, 0.f, 0.f, 0.f);
#pragma unroll
            for (int kc = 0; kc < 4; ++kc) {
#pragma unroll
                for (int grp = 0; grp < 4; ++grp) {
                    uint32_t r0, r1, r2, r3;
                    ldsm4(r0, r1, r2, r3,
                          Kb + (grp * 16 + l15) * 144 + (kc * 2 + l16) * 16);
                    uint32_t b0[2] = { r0, r2 };
                    uint32_t b1[2] = { r1, r3 };
                    mma16(sacc[2 * grp],     qf[kc], b0);
                    mma16(sacc[2 * grp + 1], qf[kc], b1);
                }
            }
            // fold softmax scale (exp2 domain)
#pragma unroll
            for (int nt = 0; nt < 8; ++nt) {
                sacc[nt].x *= SC; sacc[nt].y *= SC;
                sacc[nt].z *= SC; sacc[nt].w *= SC;
            }

            // ---- causal mask (only needed near the diagonal) ----
            if (j0 + 63 > q0 + wrow) {
                const int rg = q0 + wrow + g;
#pragma unroll
                for (int nt = 0; nt < 8; ++nt) {
                    const int cl = j0 + nt * 8 + 2 * c;
                    if (cl     > rg)     sacc[nt].x = -1e30f;
                    if (cl + 1 > rg)     sacc[nt].y = -1e30f;
                    if (cl     > rg + 8) sacc[nt].z = -1e30f;
                    if (cl + 1 > rg + 8) sacc[nt].w = -1e30f;
                }
            }

            // ---- online softmax ----
            float tm0 = -1e30f, tm1 = -1e30f;
#pragma unroll
            for (int nt = 0; nt < 8; ++nt) {
                tm0 = fmaxf(tm0, fmaxf(sacc[nt].x, sacc[nt].y));
                tm1 = fmaxf(tm1, fmaxf(sacc[nt].z, sacc[nt].w));
            }
            tm0 = fmaxf(tm0, __shfl_xor_sync(0xffffffffu, tm0, 1));
            tm0 = fmaxf(tm0, __shfl_xor_sync(0xffffffffu, tm0, 2));
            tm1 = fmaxf(tm1, __shfl_xor_sync(0xffffffffu, tm1, 1));
            tm1 = fmaxf(tm1, __shfl_xor_sync(0xffffffffu, tm1, 2));
            const float nm0 = fmaxf(m0, tm0);
            const float nm1 = fmaxf(m1, tm1);
            const float cr0 = ex2(m0 - nm0);
            const float cr1 = ex2(m1 - nm1);
            m0 = nm0; m1 = nm1;

            float ps0 = 0.f, ps1 = 0.f;
#pragma unroll
            for (int nt = 0; nt < 8; ++nt) {
                sacc[nt].x = ex2(sacc[nt].x - m0);
                sacc[nt].y = ex2(sacc[nt].y - m0);
                sacc[nt].z = ex2(sacc[nt].z - m1);
                sacc[nt].w = ex2(sacc[nt].w - m1);
                ps0 += sacc[nt].x + sacc[nt].y;
                ps1 += sacc[nt].z + sacc[nt].w;
            }
            ps0 += __shfl_xor_sync(0xffffffffu, ps0, 1);
            ps0 += __shfl_xor_sync(0xffffffffu, ps0, 2);
            ps1 += __shfl_xor_sync(0xffffffffu, ps1, 1);
            ps1 += __shfl_xor_sync(0xffffffffu, ps1, 2);
            l0 = l0 * cr0 + ps0;
            l1 = l1 * cr1 + ps1;
#pragma unroll
            for (int nt = 0; nt < 8; ++nt) {
                oacc[nt].x *= cr0; oacc[nt].y *= cr0;
                oacc[nt].z *= cr1; oacc[nt].w *= cr1;
            }

            // ---- P -> smem (fp16, warp-private rows) ----
            {
                char* pbase = fsc + (2 * KV_B);
#pragma unroll
                for (int nt = 0; nt < 8; ++nt) {
                    __half2* p0 = (__half2*)(pbase + (wrow + g) * 144 + (nt * 8 + 2 * c) * 2);
                    *p0 = __floats2half2_rn(sacc[nt].x, sacc[nt].y);
                    __half2* p1 = (__half2*)(pbase + (wrow + g + 8) * 144 + (nt * 8 + 2 * c) * 2);
                    *p1 = __floats2half2_rn(sacc[nt].z, sacc[nt].w);
                }
            }
            __syncwarp();   // warp reads back only its own 16 P rows

            // ---- O += P @ V ----
#pragma unroll
            for (int kc = 0; kc < 4; ++kc) {
                uint32_t af[4];
                ldsm4(af[0], af[1], af[2], af[3],
                      Pb + (wrow + l15) * 144 + (kc * 2 + l16) * 16);
#pragma unroll
                for (int j2 = 0; j2 < 4; ++j2) {
                    uint32_t r0, r1, r2, r3;
                    ldsm4t(r0, r1, r2, r3,
                           Vb + (kc * 16 + l15) * 144 + (j2 * 2 + l16) * 16);
                    uint32_t b0[2] = { r0, r1 };
                    uint32_t b1[2] = { r2, r3 };
                    mma16(oacc[2 * j2],     af, b0);
                    mma16(oacc[2 * j2 + 1], af, b1);
                }
            }
        }
        __syncthreads();   // all warps done with K/V before next staging
    }

    // ---- normalize + write ctx (fp16) ----
    const float il0 = 1.f / l0;
    const float il1 = 1.f / l1;
    __half* o0 = ctx + (size_t)(b * SEQ + q0 + wrow + g) * 1024 + h * 64;
    __half* o1 = o0 + 8 * 1024;
#pragma unroll
    for (int nt = 0; nt < 8; ++nt) {
        *(__half2*)(o0 + nt * 8 + 2 * c) =
            __floats2half2_rn(oacc[nt].x * il0, oacc[nt].y * il0);
        *(__half2*)(o1 + nt * 8 + 2 * c) =
            __floats2half2_rn(oacc[nt].z * il1, oacc[nt].w * il1);
    }
}

// ---------------------------------------------------------------------------
extern "C" void kernel_launch(void* const* d_in, const int* in_sizes, int n_in,
                              void* d_out, int out_size)
{
    const float* x      = (const float*)d_in[0];   // [2,2048,1024]
    const float* w_qkv  = (const float*)d_in[1];   // [1024,3072]
    const float* w_proj = (const float*)d_in[2];   // [1024,1024]
    float* out = (float*)d_out;                    // [2,2048,1024]

    __half *qkv, *ctx, *xh, *wqkvh, *wprojh;
    cudaGetSymbolAddress((void**)&qkv,    g_qkv);
    cudaGetSymbolAddress((void**)&ctx,    g_ctx);
    cudaGetSymbolAddress((void**)&xh,     g_xh);
    cudaGetSymbolAddress((void**)&wqkvh,  g_wqkvh);
    cudaGetSymbolAddress((void**)&wprojh, g_wprojh);

    cudaFuncSetAttribute(gemm_h<true>,  cudaFuncAttributeMaxDynamicSharedMemorySize, GEMM_SMEM);
    cudaFuncSetAttribute(gemm_h<false>, cudaFuncAttributeMaxDynamicSharedMemorySize, GEMM_SMEM);

    // prep: fp32 -> fp16
    f2h<<<(M_ROWS * D_MODEL / 4) / 256, 256>>>((const float4*)x, (__half2*)xh);
    f2h<<<(D_MODEL * 3 * D_MODEL / 4) / 256, 256>>>((const float4*)w_qkv, (__half2*)wqkvh);
    f2h<<<(D_MODEL * D_MODEL / 4) / 256, 256>>>((const float4*)w_proj, (__half2*)wprojh);

    // 1) QKV GEMM: [4096,1024] @ [1024,3072] -> fp16 qkv
    gemm_h<true><<<dim3(3 * D_MODEL / 128, M_ROWS / 128), 256, GEMM_SMEM>>>(
        xh, wqkvh, qkv, 3 * D_MODEL);

    // 2) Causal flash attention -> fp16 ctx
    fa_h<<<dim3(SEQ / 128, BATCH * N_HEADS), 256, FA_SMEM>>>(qkv, ctx);

    // 3) Projection GEMM: [4096,1024] @ [1024,1024] -> fp32 out
    gemm_h<false><<<dim3(D_MODEL / 128, M_ROWS / 128), 256, GEMM_SMEM>>>(
        ctx, wprojh, out, D_MODEL);
}

// round 6
// speedup vs baseline: 7.9947x; 1.0470x over previous
#include <cuda_runtime.h>
#include <cuda_fp16.h>
#include <cstdint>
#include <cstddef>

#define D_MODEL 1024
#define N_HEADS 16
#define D_HEAD 64
#define BATCH 2
#define SEQ 2048
#define M_ROWS (BATCH * SEQ)   // 4096

// Scratch (allocation-free rule: device globals)
__device__ __half g_qkv[(size_t)M_ROWS * 3 * D_MODEL];     // [4096,3072] fp16
__device__ __half g_ctx[(size_t)M_ROWS * D_MODEL];         // [4096,1024] fp16
__device__ __half g_xh[(size_t)M_ROWS * D_MODEL];          // fp16(x)
__device__ __half g_wqkvh[(size_t)D_MODEL * 3 * D_MODEL];  // fp16(w_qkv) [K,N]
__device__ __half g_wprojh[(size_t)D_MODEL * D_MODEL];     // fp16(w_proj) [K,N]

// ---------------------------------------------------------------------------
// helpers
// ---------------------------------------------------------------------------
__device__ __forceinline__ float ex2(float x) {
    float r;
    asm("ex2.approx.ftz.f32 %0, %1;" : "=f"(r) : "f"(x));
    return r;
}
__device__ __forceinline__ void cpa16(uint32_t dst, const void* src) {
    asm volatile("cp.async.cg.shared.global [%0], [%1], 16;\n" :: "r"(dst), "l"(src));
}
__device__ __forceinline__ uint32_t sm_u32(const void* p) {
    return (uint32_t)__cvta_generic_to_shared(p);
}
__device__ __forceinline__ void ldsm4(uint32_t& r0, uint32_t& r1, uint32_t& r2, uint32_t& r3,
                                      uint32_t addr) {
    asm volatile("ldmatrix.sync.aligned.m8n8.x4.shared.b16 {%0,%1,%2,%3}, [%4];"
                 : "=r"(r0), "=r"(r1), "=r"(r2), "=r"(r3) : "r"(addr));
}
__device__ __forceinline__ void ldsm4t(uint32_t& r0, uint32_t& r1, uint32_t& r2, uint32_t& r3,
                                       uint32_t addr) {
    asm volatile("ldmatrix.sync.aligned.m8n8.x4.trans.shared.b16 {%0,%1,%2,%3}, [%4];"
                 : "=r"(r0), "=r"(r1), "=r"(r2), "=r"(r3) : "r"(addr));
}
// D += A @ B  (m16n8k16, fp16 in, fp32 accumulate)
__device__ __forceinline__ void mma16(float4& d, const uint32_t* a, const uint32_t* b) {
    asm volatile(
        "mma.sync.aligned.m16n8k16.row.col.f32.f16.f16.f32 "
        "{%0,%1,%2,%3},{%4,%5,%6,%7},{%8,%9},{%0,%1,%2,%3};"
        : "+f"(d.x), "+f"(d.y), "+f"(d.z), "+f"(d.w)
        : "r"(a[0]), "r"(a[1]), "r"(a[2]), "r"(a[3]),
          "r"(b[0]), "r"(b[1]));
}

// ---------------------------------------------------------------------------
// prep: fp32 -> fp16 convert (4 elems / thread)
// ---------------------------------------------------------------------------
__global__ void f2h(const float4* __restrict__ in, __half2* __restrict__ out) {
    const int i = blockIdx.x * blockDim.x + threadIdx.x;
    float4 v = in[i];
    out[i * 2]     = __floats2half2_rn(v.x, v.y);
    out[i * 2 + 1] = __floats2half2_rn(v.z, v.w);
}

// ---------------------------------------------------------------------------
// GEMM: C[M,N] = A[M,1024] @ B[1024,N], fp16 in, fp32 accum, fp16/fp32 out.
// 128x128x32 block tile, 8 warps (2x4), warp tile 64x32, 4-stage cp.async.
// A smem: [128 rows][stride 40 fp16] (80B rows; banks 20r+4c partition 32)
// B smem: [32 k][128 n fp16], 16B chunk swizz ch^(k&7) (conflict-free trans)
// ---------------------------------------------------------------------------
#define GSTAGES 4
#define A_STB (128 * 80)    // 10240 B / stage
#define B_STB (32 * 256)    // 8192 B / stage
#define GEMM_SMEM (GSTAGES * (A_STB + B_STB))   // 73728 B

template<bool HALF_OUT>
__global__ __launch_bounds__(256, 2)
void gemm_h(const __half* __restrict__ A, const __half* __restrict__ B,
            void* __restrict__ Cv, int N)
{
    extern __shared__ char smc[];
    const uint32_t Ab = sm_u32(smc);
    const uint32_t Bb = Ab + GSTAGES * A_STB;

    const int tid  = threadIdx.x;
    const int lane = tid & 31;
    const int warp = tid >> 5;
    const int g    = lane >> 2;
    const int c    = lane & 3;
    const int l15  = lane & 15;
    const int l16  = lane >> 4;
    const int wm   = (warp & 1) * 64;
    const int wn   = (warp >> 1) * 32;
    const int m0   = blockIdx.y * 128;
    const int n0   = blockIdx.x * 128;

    auto stage = [&](int ch) {
        const int s  = ch & 3;
        const int k0 = ch * 32;
#pragma unroll
        for (int i = 0; i < 2; ++i) {              // A: 128 rows x 4 chunks
            const int id = tid + 256 * i;
            const int row = id >> 2, cc = id & 3;
            cpa16(Ab + s * A_STB + row * 80 + cc * 16,
                  A + (size_t)(m0 + row) * 1024 + k0 + cc * 8);
        }
#pragma unroll
        for (int i = 0; i < 2; ++i) {              // B: 32 k x 16 chunks
            const int id = tid + 256 * i;
            const int row = id >> 4, cc = id & 15;
            cpa16(Bb + s * B_STB + row * 256 + ((cc ^ (row & 7)) * 16),
                  B + (size_t)(k0 + row) * N + n0 + cc * 8);
        }
    };

    stage(0); asm volatile("cp.async.commit_group;\n");
    stage(1); asm volatile("cp.async.commit_group;\n");
    stage(2); asm volatile("cp.async.commit_group;\n");

    float4 acc[4][4];
#pragma unroll
    for (int i = 0; i < 4; ++i)
#pragma unroll
        for (int j = 0; j < 4; ++j) acc[i][j] = make_float4(0.f, 0.f, 0.f, 0.f);

    for (int ch = 0; ch < 32; ++ch) {
        asm volatile("cp.async.wait_group %0;\n" :: "n"(2));
        __syncthreads();

        if (ch + 3 < 32) stage(ch + 3);
        asm volatile("cp.async.commit_group;\n");

        const uint32_t As = Ab + (ch & 3) * A_STB;
        const uint32_t Bs = Bb + (ch & 3) * B_STB;

#pragma unroll
        for (int kc = 0; kc < 2; ++kc) {
            uint32_t af[4][4];
#pragma unroll
            for (int i = 0; i < 4; ++i)
                ldsm4(af[i][0], af[i][1], af[i][2], af[i][3],
                      As + (wm + i * 16 + l15) * 80 + (kc * 2 + l16) * 16);
            uint32_t bf[4][2];
#pragma unroll
            for (int j2 = 0; j2 < 2; ++j2) {
                const int krow = kc * 16 + l15;
                const int cn   = (wn >> 3) + j2 * 2 + l16;
                ldsm4t(bf[j2 * 2][0], bf[j2 * 2][1], bf[j2 * 2 + 1][0], bf[j2 * 2 + 1][1],
                       Bs + krow * 256 + ((cn ^ (krow & 7)) * 16));
            }
#pragma unroll
            for (int i = 0; i < 4; ++i)
#pragma unroll
                for (int j = 0; j < 4; ++j)
                    mma16(acc[i][j], af[i], bf[j]);
        }
    }

    // epilogue
#pragma unroll
    for (int i = 0; i < 4; ++i) {
        const int r = m0 + wm + i * 16 + g;
#pragma unroll
        for (int j = 0; j < 4; ++j) {
            const int cl = n0 + wn + j * 8 + 2 * c;
            if (HALF_OUT) {
                __half* C = (__half*)Cv;
                *(__half2*)&C[(size_t)r * N + cl] =
                    __floats2half2_rn(acc[i][j].x, acc[i][j].y);
                *(__half2*)&C[(size_t)(r + 8) * N + cl] =
                    __floats2half2_rn(acc[i][j].z, acc[i][j].w);
            } else {
                float* C = (float*)Cv;
                *(float2*)&C[(size_t)r * N + cl] = make_float2(acc[i][j].x, acc[i][j].y);
                *(float2*)&C[(size_t)(r + 8) * N + cl] = make_float2(acc[i][j].z, acc[i][j].w);
            }
        }
    }
}

// ---------------------------------------------------------------------------
// Flash attention, causal, fp16 mma + ldmatrix, double-buffered K/V tiles.
// Br=128 (8 warps x 16 q-rows), Bc=64. K/V staged via cp.async (fp16),
// next tile's load overlaps current tile's compute.
// K/V/P smem rows stride 72 fp16 = 144 B (conflict-free ldmatrix).
// ---------------------------------------------------------------------------
#define KV_B (64 * 144)                        // 9216 B per K / V tile
#define FA_SMEM (4 * KV_B + 128 * 144)         // 55296 B (2 K + 2 V + P)

__global__ __launch_bounds__(256, 2)
void fa_h(const __half* __restrict__ qkv, __half* __restrict__ ctx)
{
    extern __shared__ char fsc[];
    const uint32_t Kb0 = sm_u32(fsc);              // K buf 0, K buf 1
    const uint32_t Vb0 = Kb0 + 2 * KV_B;           // V buf 0, V buf 1
    const uint32_t Pb  = Kb0 + 4 * KV_B;

    const int tid  = threadIdx.x;
    const int lane = tid & 31;
    const int warp = tid >> 5;
    const int g    = lane >> 2;
    const int c    = lane & 3;
    const int l15  = lane & 15;
    const int l16  = lane >> 4;
    const int bh   = blockIdx.y;
    const int b    = bh >> 4;
    const int h    = bh & 15;
    const int q0   = (gridDim.x - 1 - blockIdx.x) * 128;   // big blocks first
    const int wrow = warp * 16;

    const __half* qbase = qkv + (size_t)(b * SEQ) * 3072 + h * 64;

    // staging: 512 chunk-slots (64 rows x 8 chunks) split over 256 threads
    const int srow = tid >> 3;            // rows 0..31 (i=0) / 32..63 (i=1)
    const int scc  = tid & 7;
    auto stage_kv = [&](int j0, int s) {
        const uint32_t kd = Kb0 + s * KV_B;
        const uint32_t vd = Vb0 + s * KV_B;
#pragma unroll
        for (int i = 0; i < 2; ++i) {
            const int row = srow + 32 * i;
            const __half* kg = qbase + (size_t)(j0 + row) * 3072 + 1024 + scc * 8;
            cpa16(kd + row * 144 + scc * 16, kg);
            cpa16(vd + row * 144 + scc * 16, kg + 1024);
        }
    };

    // Q fragments (fp16 pairs straight from gmem)
    uint32_t qf[4][4];
    {
        const __half* r0 = qbase + (size_t)(q0 + wrow + g) * 3072;
        const __half* r1 = r0 + 8 * 3072;
#pragma unroll
        for (int kc = 0; kc < 4; ++kc) {
            qf[kc][0] = *(const uint32_t*)(r0 + kc * 16 + 2 * c);
            qf[kc][1] = *(const uint32_t*)(r1 + kc * 16 + 2 * c);
            qf[kc][2] = *(const uint32_t*)(r0 + kc * 16 + 8 + 2 * c);
            qf[kc][3] = *(const uint32_t*)(r1 + kc * 16 + 8 + 2 * c);
        }
    }

    float4 oacc[8];
#pragma unroll
    for (int i = 0; i < 8; ++i) oacc[i] = make_float4(0.f, 0.f, 0.f, 0.f);
    float m0 = -1e30f, m1 = -1e30f, l0 = 0.f, l1 = 0.f;

    const float SC = 0.125f * 1.44269504088896f;   // (1/sqrt(64)) * log2(e)
    const int jmax = q0 + 64;

    // prologue: stage tile 0 into buffer 0
    stage_kv(0, 0);
    asm volatile("cp.async.commit_group;\n");

    int s = 0;
    for (int j0 = 0; j0 <= jmax; j0 += 64, s ^= 1) {
        // issue next tile into the other buffer, then wait for current tile
        if (j0 + 64 <= jmax) {
            stage_kv(j0 + 64, s ^ 1);
            asm volatile("cp.async.commit_group;\n");
            asm volatile("cp.async.wait_group 1;\n");
        } else {
            asm volatile("cp.async.wait_group 0;\n");
        }
        __syncthreads();

        const uint32_t Kb = Kb0 + s * KV_B;
        const uint32_t Vb = Vb0 + s * KV_B;

        if (j0 <= q0 + wrow + 15) {   // warp has >= 1 unmasked row in this tile
            // ---- S = Q @ K^T ----
            float4 sacc[8];
#pragma unroll
            for (int i = 0; i < 8; ++i) sacc[i] = make_float4(0.f, 0.f, 0.f, 0.f);
#pragma unroll
            for (int kc = 0; kc < 4; ++kc) {
#pragma unroll
                for (int grp = 0; grp < 4; ++grp) {
                    uint32_t r0, r1, r2, r3;
                    ldsm4(r0, r1, r2, r3,
                          Kb + (grp * 16 + l15) * 144 + (kc * 2 + l16) * 16);
                    uint32_t b0[2] = { r0, r2 };
                    uint32_t b1[2] = { r1, r3 };
                    mma16(sacc[2 * grp],     qf[kc], b0);
                    mma16(sacc[2 * grp + 1], qf[kc], b1);
                }
            }
            // fold softmax scale (exp2 domain)
#pragma unroll
            for (int nt = 0; nt < 8; ++nt) {
                sacc[nt].x *= SC; sacc[nt].y *= SC;
                sacc[nt].z *= SC; sacc[nt].w *= SC;
            }

            // ---- causal mask (only needed near the diagonal) ----
            if (j0 + 63 > q0 + wrow) {
                const int rg = q0 + wrow + g;
#pragma unroll
                for (int nt = 0; nt < 8; ++nt) {
                    const int cl = j0 + nt * 8 + 2 * c;
                    if (cl     > rg)     sacc[nt].x = -1e30f;
                    if (cl + 1 > rg)     sacc[nt].y = -1e30f;
                    if (cl     > rg + 8) sacc[nt].z = -1e30f;
                    if (cl + 1 > rg + 8) sacc[nt].w = -1e30f;
                }
            }

            // ---- online softmax ----
            float tm0 = -1e30f, tm1 = -1e30f;
#pragma unroll
            for (int nt = 0; nt < 8; ++nt) {
                tm0 = fmaxf(tm0, fmaxf(sacc[nt].x, sacc[nt].y));
                tm1 = fmaxf(tm1, fmaxf(sacc[nt].z, sacc[nt].w));
            }
            tm0 = fmaxf(tm0, __shfl_xor_sync(0xffffffffu, tm0, 1));
            tm0 = fmaxf(tm0, __shfl_xor_sync(0xffffffffu, tm0, 2));
            tm1 = fmaxf(tm1, __shfl_xor_sync(0xffffffffu, tm1, 1));
            tm1 = fmaxf(tm1, __shfl_xor_sync(0xffffffffu, tm1, 2));
            const float nm0 = fmaxf(m0, tm0);
            const float nm1 = fmaxf(m1, tm1);
            const float cr0 = ex2(m0 - nm0);
            const float cr1 = ex2(m1 - nm1);
            m0 = nm0; m1 = nm1;

            float ps0 = 0.f, ps1 = 0.f;
#pragma unroll
            for (int nt = 0; nt < 8; ++nt) {
                sacc[nt].x = ex2(sacc[nt].x - m0);
                sacc[nt].y = ex2(sacc[nt].y - m0);
                sacc[nt].z = ex2(sacc[nt].z - m1);
                sacc[nt].w = ex2(sacc[nt].w - m1);
                ps0 += sacc[nt].x + sacc[nt].y;
                ps1 += sacc[nt].z + sacc[nt].w;
            }
            ps0 += __shfl_xor_sync(0xffffffffu, ps0, 1);
            ps0 += __shfl_xor_sync(0xffffffffu, ps0, 2);
            ps1 += __shfl_xor_sync(0xffffffffu, ps1, 1);
            ps1 += __shfl_xor_sync(0xffffffffu, ps1, 2);
            l0 = l0 * cr0 + ps0;
            l1 = l1 * cr1 + ps1;
#pragma unroll
            for (int nt = 0; nt < 8; ++nt) {
                oacc[nt].x *= cr0; oacc[nt].y *= cr0;
                oacc[nt].z *= cr1; oacc[nt].w *= cr1;
            }

            // ---- P -> smem (fp16, warp-private rows) ----
            {
                char* pbase = fsc + 4 * KV_B;
#pragma unroll
                for (int nt = 0; nt < 8; ++nt) {
                    __half2* p0 = (__half2*)(pbase + (wrow + g) * 144 + (nt * 8 + 2 * c) * 2);
                    *p0 = __floats2half2_rn(sacc[nt].x, sacc[nt].y);
                    __half2* p1 = (__half2*)(pbase + (wrow + g + 8) * 144 + (nt * 8 + 2 * c) * 2);
                    *p1 = __floats2half2_rn(sacc[nt].z, sacc[nt].w);
                }
            }
            __syncwarp();   // warp reads back only its own 16 P rows

            // ---- O += P @ V ----
#pragma unroll
            for (int kc = 0; kc < 4; ++kc) {
                uint32_t af[4];
                ldsm4(af[0], af[1], af[2], af[3],
                      Pb + (wrow + l15) * 144 + (kc * 2 + l16) * 16);
#pragma unroll
                for (int j2 = 0; j2 < 4; ++j2) {
                    uint32_t r0, r1, r2, r3;
                    ldsm4t(r0, r1, r2, r3,
                           Vb + (kc * 16 + l15) * 144 + (j2 * 2 + l16) * 16);
                    uint32_t b0[2] = { r0, r1 };
                    uint32_t b1[2] = { r2, r3 };
                    mma16(oacc[2 * j2],     af, b0);
                    mma16(oacc[2 * j2 + 1], af, b1);
                }
            }
        }
        __syncthreads();   // all warps done with buffer s before it is re-staged
    }

    // ---- normalize + write ctx (fp16) ----
    const float il0 = 1.f / l0;
    const float il1 = 1.f / l1;
    __half* o0 = ctx + (size_t)(b * SEQ + q0 + wrow + g) * 1024 + h * 64;
    __half* o1 = o0 + 8 * 1024;
#pragma unroll
    for (int nt = 0; nt < 8; ++nt) {
        *(__half2*)(o0 + nt * 8 + 2 * c) =
            __floats2half2_rn(oacc[nt].x * il0, oacc[nt].y * il0);
        *(__half2*)(o1 + nt * 8 + 2 * c) =
            __floats2half2_rn(oacc[nt].z * il1, oacc[nt].w * il1);
    }
}

// ---------------------------------------------------------------------------
extern "C" void kernel_launch(void* const* d_in, const int* in_sizes, int n_in,
                              void* d_out, int out_size)
{
    const float* x      = (const float*)d_in[0];   // [2,2048,1024]
    const float* w_qkv  = (const float*)d_in[1];   // [1024,3072]
    const float* w_proj = (const float*)d_in[2];   // [1024,1024]
    float* out = (float*)d_out;                    // [2,2048,1024]

    __half *qkv, *ctx, *xh, *wqkvh, *wprojh;
    cudaGetSymbolAddress((void**)&qkv,    g_qkv);
    cudaGetSymbolAddress((void**)&ctx,    g_ctx);
    cudaGetSymbolAddress((void**)&xh,     g_xh);
    cudaGetSymbolAddress((void**)&wqkvh,  g_wqkvh);
    cudaGetSymbolAddress((void**)&wprojh, g_wprojh);

    cudaFuncSetAttribute(gemm_h<true>,  cudaFuncAttributeMaxDynamicSharedMemorySize, GEMM_SMEM);
    cudaFuncSetAttribute(gemm_h<false>, cudaFuncAttributeMaxDynamicSharedMemorySize, GEMM_SMEM);
    cudaFuncSetAttribute(fa_h, cudaFuncAttributeMaxDynamicSharedMemorySize, FA_SMEM);

    // prep: fp32 -> fp16
    f2h<<<(M_ROWS * D_MODEL / 4) / 256, 256>>>((const float4*)x, (__half2*)xh);
    f2h<<<(D_MODEL * 3 * D_MODEL / 4) / 256, 256>>>((const float4*)w_qkv, (__half2*)wqkvh);
    f2h<<<(D_MODEL * D_MODEL / 4) / 256, 256>>>((const float4*)w_proj, (__half2*)wprojh);

    // 1) QKV GEMM: [4096,1024] @ [1024,3072] -> fp16 qkv
    gemm_h<true><<<dim3(3 * D_MODEL / 128, M_ROWS / 128), 256, GEMM_SMEM>>>(
        xh, wqkvh, qkv, 3 * D_MODEL);

    // 2) Causal flash attention -> fp16 ctx
    fa_h<<<dim3(SEQ / 128, BATCH * N_HEADS), 256, FA_SMEM>>>(qkv, ctx);

    // 3) Projection GEMM: [4096,1024] @ [1024,1024] -> fp32 out
    gemm_h<false><<<dim3(D_MODEL / 128, M_ROWS / 128), 256, GEMM_SMEM>>>(
        ctx, wprojh, out, D_MODEL);
}